// round 6
// baseline (speedup 1.0000x reference)
#include <cuda_runtime.h>

#define NN    2048
#define HALF  1024
#define F     128
#define LATD  64
#define ES    65536
#define KS    8
#define NB    148
#define NT    256

// ---------------- scratch (device globals, zero-initialized) ----------------
__device__ unsigned g_zbuf[HALF + NN];   // [0,1024) colsum f32, [1024,3072) cnt i32
__device__ float g_S[HALF * HALF];
__device__ float g_dinv[NN];
__device__ int   g_ptr[NN + 1];
__device__ int   g_cur[NN];
__device__ int   g_csrc[ES];
__device__ float g_h[NN * F];
__device__ float g_hsd[NN * F];
__device__ float g_acc[NN * F];
__device__ float g_part[KS * HALF * F];

__device__ int          g_bar_cnt = 0;
__device__ volatile int g_bar_gen = 0;

// ---------------- grid barrier (148 co-resident blocks) ----------------
__device__ __forceinline__ void gbar() {
    __syncthreads();
    if (threadIdx.x == 0) {
        int gen = g_bar_gen;
        __threadfence();
        if (atomicAdd(&g_bar_cnt, 1) == NB - 1) {
            g_bar_cnt = 0;
            __threadfence();
            g_bar_gen = gen + 1;
        } else {
            while (g_bar_gen == gen) { }
        }
        __threadfence();
    }
    __syncthreads();
}

// ---------------- packed f32x2 helpers (SASS FFMA2) ----------------
__device__ __forceinline__ unsigned long long pk2(float lo, float hi) {
    unsigned long long r;
    asm("mov.b64 %0, {%1, %2};" : "=l"(r) : "f"(lo), "f"(hi));
    return r;
}
__device__ __forceinline__ float2 upk2(unsigned long long v) {
    float2 f;
    asm("mov.b64 {%0, %1}, %2;" : "=f"(f.x), "=f"(f.y) : "l"(v));
    return f;
}
__device__ __forceinline__ void fma2(unsigned long long& c,
                                     unsigned long long a, unsigned long long b) {
    asm("fma.rn.f32x2 %0, %1, %2, %3;" : "=l"(c) : "l"(a), "l"(b), "l"(c));
}

// ---------------- aggregation phase (dense partials + edge CSR) ----------
__device__ __forceinline__ void agg_phase(const float* __restrict__ in,
                                          float* sA, float* sB) {
    int tid = threadIdx.x;
    for (int t = blockIdx.x; t < 640; t += NB) {
        if (t < 128) {
            // dense: g_part[split][c0:c0+64, :] = S^T-slice @ in
            int c0 = (t & 15) * 64;
            int split = t >> 4;
            int kbase = split * 128;
            int tx = tid & 15, ty = tid >> 4;
            unsigned long long acc[4][4] = {};
            for (int k0 = kbase; k0 < kbase + 128; k0 += 16) {
                for (int l = tid; l < 64 * 16; l += NT) {
                    int kk = l >> 6, i = l & 63;
                    sA[kk * 65 + i] = g_S[(k0 + kk) * HALF + c0 + i];
                }
                for (int l = tid; l < 16 * 128; l += NT) {
                    int kk = l >> 7, f = l & 127;
                    sB[kk * 128 + f] = in[(k0 + kk) * F + f];
                }
                __syncthreads();
#pragma unroll
                for (int kk = 0; kk < 16; kk++) {
                    unsigned long long ad[4], bb[4];
#pragma unroll
                    for (int m = 0; m < 4; m++) { float a = sA[kk * 65 + ty + m * 16]; ad[m] = pk2(a, a); }
                    const float2* brow = (const float2*)(sB + kk * 128);
#pragma unroll
                    for (int n = 0; n < 4; n++) { float2 bv = brow[tx + n * 16]; bb[n] = pk2(bv.x, bv.y); }
#pragma unroll
                    for (int m = 0; m < 4; m++)
#pragma unroll
                        for (int n = 0; n < 4; n++) fma2(acc[m][n], ad[m], bb[n]);
                }
                __syncthreads();
            }
            float* dst = g_part + split * HALF * F;
#pragma unroll
            for (int m = 0; m < 4; m++) {
                int c = c0 + ty + m * 16;
#pragma unroll
                for (int n = 0; n < 4; n++) {
                    float2 v = upk2(acc[m][n]);
                    int f = 2 * (tx + n * 16);
                    dst[c * F + f]     = v.x;
                    dst[c * F + f + 1] = v.y;
                }
            }
        } else {
            // edge: 4 nodes per tile, 64 lanes per node, float2 per lane
            int node = (t - 128) * 4 + (tid >> 6);
            int f2 = tid & 63;
            const float2* in2 = (const float2*)in;
            float2 acc = in2[node * 64 + f2];           // self loop (pre-scaled)
            int p = g_ptr[node], p1 = g_ptr[node + 1];
            for (; p + 8 <= p1; p += 8) {
                int s0 = g_csrc[p],     s1 = g_csrc[p + 1], s2 = g_csrc[p + 2], s3 = g_csrc[p + 3];
                int s4 = g_csrc[p + 4], s5 = g_csrc[p + 5], s6 = g_csrc[p + 6], s7 = g_csrc[p + 7];
                float2 v0 = in2[s0 * 64 + f2], v1 = in2[s1 * 64 + f2];
                float2 v2 = in2[s2 * 64 + f2], v3 = in2[s3 * 64 + f2];
                float2 v4 = in2[s4 * 64 + f2], v5 = in2[s5 * 64 + f2];
                float2 v6 = in2[s6 * 64 + f2], v7 = in2[s7 * 64 + f2];
                acc.x += ((v0.x + v1.x) + (v2.x + v3.x)) + ((v4.x + v5.x) + (v6.x + v7.x));
                acc.y += ((v0.y + v1.y) + (v2.y + v3.y)) + ((v4.y + v5.y) + (v6.y + v7.y));
            }
            for (; p < p1; p++) {
                float2 v = in2[g_csrc[p] * 64 + f2];
                acc.x += v.x; acc.y += v.y;
            }
            ((float2*)g_acc)[node * 64 + f2] = acc;
        }
    }
}

// ================= the one persistent kernel ================================
__global__ void __launch_bounds__(NT) k_mega(
        const float* __restrict__ my,  const int* __restrict__ ei,
        const float* __restrict__ x,   const float* __restrict__ W1,
        const float* __restrict__ b1,
        const float* __restrict__ Wmu, const float* __restrict__ bmu,
        const float* __restrict__ Wls, const float* __restrict__ bls,
        float* __restrict__ out) {
    __shared__ float sA[16 * 65];
    __shared__ float sB[16 * 128];
    int tid = threadIdx.x;
    int bx = blockIdx.x;

    // ---- P0: zero counters ----
    {
        int i = bx * NT + tid;
        if (i < HALF + NN) g_zbuf[i] = 0u;
    }
    gbar();

    // ---- P1: sigmoid+colsum | sparse count | gemm1 (x@W1) ----
    for (int t = bx; t < 1344; t += NB) {
        if (t < 1024) {
            int r0 = (t >> 5) * 32, c0 = (t & 31) * 32;
            int tx = tid & 31, ty = tid >> 5;
            int c = c0 + tx;
            float csum = 0.f;
#pragma unroll
            for (int rr = 0; rr < 4; rr++) {
                int r = r0 + ty + rr * 8;
                float v = 1.0f / (1.0f + __expf(-my[r * 2048 + c]));
                g_S[r * HALF + c] = v;
                csum += v;
            }
            sA[tid] = csum;
            __syncthreads();
            if (ty < 4) sA[tid] += sA[tid + 128];
            __syncthreads();
            if (ty < 2) sA[tid] += sA[tid + 64];
            __syncthreads();
            if (ty == 0) atomicAdd(&((float*)g_zbuf)[c], sA[tid] + sA[tid + 32]);
            __syncthreads();
        } else if (t < 1280) {
            int e = (t - 1024) * 256 + tid;
            atomicAdd((int*)g_zbuf + HALF + ei[ES + e], 1);
        } else {
            int bid = t - 1280;
            int col0 = (bid & 1) * 64;
            int row0 = (bid >> 1) * 64;
            int tx = tid & 15, ty = tid >> 4;
            unsigned long long acc[4][2] = {};
            for (int k0 = 0; k0 < 128; k0 += 16) {
                for (int l = tid; l < 64 * 16; l += NT) {
                    int i = l >> 4, kk = l & 15;
                    sA[kk * 65 + i] = x[(row0 + i) * 128 + k0 + kk];
                }
                for (int l = tid; l < 16 * 64; l += NT) {
                    int kk = l >> 6, j = l & 63;
                    sB[kk * 64 + j] = W1[(k0 + kk) * 128 + col0 + j];
                }
                __syncthreads();
#pragma unroll
                for (int kk = 0; kk < 16; kk++) {
                    unsigned long long ad[4], bb[2];
#pragma unroll
                    for (int m = 0; m < 4; m++) { float a = sA[kk * 65 + ty + m * 16]; ad[m] = pk2(a, a); }
                    const float2* brow = (const float2*)(sB + kk * 64);
#pragma unroll
                    for (int n = 0; n < 2; n++) { float2 bv = brow[tx + n * 16]; bb[n] = pk2(bv.x, bv.y); }
#pragma unroll
                    for (int m = 0; m < 4; m++)
#pragma unroll
                        for (int n = 0; n < 2; n++) fma2(acc[m][n], ad[m], bb[n]);
                }
                __syncthreads();
            }
#pragma unroll
            for (int m = 0; m < 4; m++) {
                int r = row0 + ty + m * 16;
#pragma unroll
                for (int n = 0; n < 2; n++) {
                    float2 v = upk2(acc[m][n]);
                    int cc = col0 + 2 * (tx + n * 16);
                    g_h[r * 128 + cc]     = v.x;
                    g_h[r * 128 + cc + 1] = v.y;
                }
            }
        }
    }
    gbar();

    // ---- P2: block 0: CSR scan; blocks 1..8: dinv ----
    if (bx == 0) {
        const int* cnt = (const int*)g_zbuf + HALF;
        int c[8]; int s = 0;
#pragma unroll
        for (int j = 0; j < 8; j++) { c[j] = cnt[tid * 8 + j]; s += c[j]; }
        int lane = tid & 31, w = tid >> 5;
        int v = s;
#pragma unroll
        for (int off = 1; off < 32; off <<= 1) {
            int u = __shfl_up_sync(0xffffffffu, v, off);
            if (lane >= off) v += u;
        }
        __shared__ int wsum[8];
        if (lane == 31) wsum[w] = v;
        __syncthreads();
        if (tid < 8) {
            int xx = wsum[tid];
#pragma unroll
            for (int off = 1; off < 8; off <<= 1) {
                int u = __shfl_up_sync(0xffu, xx, off);
                if (tid >= off) xx += u;
            }
            wsum[tid] = xx;
        }
        __syncthreads();
        int run = (w > 0 ? wsum[w - 1] : 0) + v - s;   // exclusive prefix
#pragma unroll
        for (int j = 0; j < 8; j++) {
            g_ptr[tid * 8 + j] = run;
            g_cur[tid * 8 + j] = run;
            run += c[j];
        }
        if (tid == 255) g_ptr[NN] = ES;
    } else if (bx <= 8) {
        int i = (bx - 1) * NT + tid;                    // covers 0..2047
        const int* cnt = (const int*)g_zbuf + HALF;
        const float* colsum = (const float*)g_zbuf;
        float deg = 1.0f + (float)cnt[i] + (i < HALF ? colsum[i] : 0.f);
        g_dinv[i] = rsqrtf(deg);
    }
    gbar();

    // ---- P3: CSR fill | hsd = dinv * h ----
    for (int t = bx; t < 512; t += NB) {
        if (t < 256) {
            int e = t * 256 + tid;
            int dst = ei[ES + e];
            int pos = atomicAdd(&g_cur[dst], 1);
            g_csrc[pos] = ei[e];
        } else {
            int idx = (t - 256) * 256 + tid;            // float4 index
            float d = g_dinv[idx >> 5];
            float4 a = ((const float4*)g_h)[idx];
            a.x *= d; a.y *= d; a.z *= d; a.w *= d;
            ((float4*)g_hsd)[idx] = a;
        }
    }
    gbar();

    // ---- P4: aggregation pass 1 ----
    agg_phase(g_hsd, sA, sB);
    gbar();

    // ---- P5: fin1: reduce partials; hsd = dinv*relu(dinv*acc + b1) ----
    for (int t = bx; t < 256; t += NB) {
        int idx = t * 256 + tid;                        // float4 index
        float4 a = ((const float4*)g_acc)[idx];
        if (idx < HALF * F / 4) {
#pragma unroll
            for (int s = 0; s < KS; s++) {
                float4 pp = ((const float4*)g_part)[s * (HALF * F / 4) + idx];
                a.x += pp.x; a.y += pp.y; a.z += pp.z; a.w += pp.w;
            }
        }
        float d = g_dinv[idx >> 5];
        int cb = (idx & 31) * 4;
        float4 o;
        o.x = d * fmaxf(d * a.x + b1[cb],     0.f);
        o.y = d * fmaxf(d * a.y + b1[cb + 1], 0.f);
        o.z = d * fmaxf(d * a.z + b1[cb + 2], 0.f);
        o.w = d * fmaxf(d * a.w + b1[cb + 3], 0.f);
        ((float4*)g_hsd)[idx] = o;
    }
    gbar();

    // ---- P6: aggregation pass 2 ----
    agg_phase(g_hsd, sA, sB);
    gbar();

    // ---- P7: out: [z_mu | z_logstd] = dinv*(acc + Σpart) @ [Wmu|Wls] + bias -
    for (int t = bx; t < 64; t += NB) {
        int row0 = t * 32;
        bool firsthalf = row0 < HALF;
        int tx = tid & 15, ty = tid >> 4;
        unsigned long long acc[2][4] = {};
        for (int k0 = 0; k0 < 128; k0 += 16) {
            for (int l = tid; l < 32 * 16; l += NT) {
                int i = l >> 4, kk = l & 15;
                int r = row0 + i;
                float v = g_acc[r * F + k0 + kk];
                if (firsthalf) {
#pragma unroll
                    for (int s = 0; s < KS; s++) v += g_part[s * HALF * F + r * F + k0 + kk];
                }
                sA[kk * 33 + i] = v * g_dinv[r];
            }
            for (int l = tid; l < 16 * 128; l += NT) {
                int kk = l >> 7, j = l & 127;
                sB[kk * 128 + j] = (j < 64) ? Wmu[(k0 + kk) * LATD + j]
                                            : Wls[(k0 + kk) * LATD + (j - 64)];
            }
            __syncthreads();
#pragma unroll
            for (int kk = 0; kk < 16; kk++) {
                unsigned long long ad[2], bb[4];
#pragma unroll
                for (int m = 0; m < 2; m++) { float a = sA[kk * 33 + ty + m * 16]; ad[m] = pk2(a, a); }
                const float2* brow = (const float2*)(sB + kk * 128);
#pragma unroll
                for (int n = 0; n < 4; n++) { float2 bv = brow[tx + n * 16]; bb[n] = pk2(bv.x, bv.y); }
#pragma unroll
                for (int m = 0; m < 2; m++)
#pragma unroll
                    for (int n = 0; n < 4; n++) fma2(acc[m][n], ad[m], bb[n]);
            }
            __syncthreads();
        }
#pragma unroll
        for (int m = 0; m < 2; m++) {
            int r = row0 + ty + m * 16;
#pragma unroll
            for (int n = 0; n < 4; n++) {
                float2 v = upk2(acc[m][n]);
                int j = 2 * (tx + n * 16);              // pairs never cross 64
                if (j < 64) {
                    out[r * LATD + j]     = v.x + bmu[j];
                    out[r * LATD + j + 1] = v.y + bmu[j + 1];
                } else {
                    int jj = j - 64;
                    out[NN * LATD + r * LATD + jj]     = v.x + bls[jj];
                    out[NN * LATD + r * LATD + jj + 1] = v.y + bls[jj + 1];
                }
            }
        }
    }
}

// ================= launch: ONE node ========================================
extern "C" void kernel_launch(void* const* d_in, const int* in_sizes, int n_in,
                              void* d_out, int out_size) {
    const float* x   = (const float*)d_in[0];
    const float* my  = (const float*)d_in[1];
    const float* W1  = (const float*)d_in[2];
    const float* b1  = (const float*)d_in[3];
    const float* Wmu = (const float*)d_in[4];
    const float* bmu = (const float*)d_in[5];
    const float* Wls = (const float*)d_in[6];
    const float* bls = (const float*)d_in[7];
    const int*   ei  = (const int*)d_in[8];
    float* out = (float*)d_out;

    k_mega<<<NB, NT>>>(my, ei, x, W1, b1, Wmu, bmu, Wls, bls, out);
}

// round 7
// speedup vs baseline: 1.4200x; 1.4200x over previous
#include <cuda_runtime.h>

#define NN    2048
#define HALF  1024
#define F     128
#define LATD  64
#define ES    65536

// ---------------- scratch (device globals) ----------------
__device__ unsigned g_zbuf[HALF + NN];   // [0,1024) colsum f32, [1024,3072) cnt i32
__device__ float g_S[HALF * HALF];       // tf32-rounded sigmoid(my[r,c]) at [r*1024+c]
__device__ float g_dinv[NN];
__device__ int   g_ptr[NN + 1];
__device__ int   g_cur[NN];
__device__ int   g_csrc[ES];
__device__ float g_h[NN * F];
__device__ float g_hsd[NN * F];
__device__ float g_acc[NN * F];

// ---------------- packed f32x2 helpers (SASS FFMA2) ----------------
__device__ __forceinline__ unsigned long long pk2(float lo, float hi) {
    unsigned long long r;
    asm("mov.b64 %0, {%1, %2};" : "=l"(r) : "f"(lo), "f"(hi));
    return r;
}
__device__ __forceinline__ float2 upk2(unsigned long long v) {
    float2 f;
    asm("mov.b64 {%0, %1}, %2;" : "=f"(f.x), "=f"(f.y) : "l"(v));
    return f;
}
__device__ __forceinline__ void fma2(unsigned long long& c,
                                     unsigned long long a, unsigned long long b) {
    asm("fma.rn.f32x2 %0, %1, %2, %3;" : "=l"(c) : "l"(a), "l"(b), "l"(c));
}
__device__ __forceinline__ float cvt_tf32(float v) {
    unsigned u;
    asm("cvt.rna.tf32.f32 %0, %1;" : "=r"(u) : "f"(v));
    return __uint_as_float(u);
}

// ================= mega kernel A: sigmoid+colsum | sparse count | gemm1 ======
__global__ void k_megaA(const float* __restrict__ my, const int* __restrict__ ei,
                        const float* __restrict__ x, const float* __restrict__ W1) {
    int b = blockIdx.x;
    int tid = threadIdx.x;
    if (b < 1024) {
        __shared__ float sm[256];
        int r0 = (b >> 5) * 32, c0 = (b & 31) * 32;
        int tx = tid & 31, ty = tid >> 5;
        int c = c0 + tx;
        float csum = 0.f;
#pragma unroll
        for (int rr = 0; rr < 4; rr++) {
            int r = r0 + ty + rr * 8;
            float v = cvt_tf32(1.0f / (1.0f + __expf(-my[r * 2048 + c])));
            g_S[r * HALF + c] = v;
            csum += v;
        }
        sm[tid] = csum;
        __syncthreads();
        if (ty < 4) sm[tid] += sm[tid + 128];
        __syncthreads();
        if (ty < 2) sm[tid] += sm[tid + 64];
        __syncthreads();
        if (ty == 0) atomicAdd(&((float*)g_zbuf)[c], sm[tid] + sm[tid + 32]);
    } else if (b < 1280) {
        int e = (b - 1024) * 256 + tid;
        atomicAdd((int*)g_zbuf + HALF + ei[ES + e], 1);
    } else {
        __shared__ float As[16][65];
        __shared__ float Bs[16 * 64];
        int bid = b - 1280;
        int col0 = (bid & 1) * 64;
        int row0 = (bid >> 1) * 64;
        int tx = tid & 15, ty = tid >> 4;
        unsigned long long acc[4][2] = {};
        for (int k0 = 0; k0 < 128; k0 += 16) {
            for (int l = tid; l < 64 * 16; l += 256) {
                int i = l >> 4, kk = l & 15;
                As[kk][i] = x[(row0 + i) * 128 + k0 + kk];
            }
            for (int l = tid; l < 16 * 64; l += 256) {
                int kk = l >> 6, j = l & 63;
                Bs[kk * 64 + j] = W1[(k0 + kk) * 128 + col0 + j];
            }
            __syncthreads();
#pragma unroll
            for (int kk = 0; kk < 16; kk++) {
                unsigned long long ad[4], bb[2];
#pragma unroll
                for (int m = 0; m < 4; m++) { float a = As[kk][ty + m * 16]; ad[m] = pk2(a, a); }
                const float2* brow = (const float2*)(Bs + kk * 64);
#pragma unroll
                for (int n = 0; n < 2; n++) { float2 bv = brow[tx + n * 16]; bb[n] = pk2(bv.x, bv.y); }
#pragma unroll
                for (int m = 0; m < 4; m++)
#pragma unroll
                    for (int n = 0; n < 2; n++) fma2(acc[m][n], ad[m], bb[n]);
            }
            __syncthreads();
        }
#pragma unroll
        for (int m = 0; m < 4; m++) {
            int r = row0 + ty + m * 16;
#pragma unroll
            for (int n = 0; n < 2; n++) {
                float2 v = upk2(acc[m][n]);
                int cc = col0 + 2 * (tx + n * 16);
                g_h[r * 128 + cc]     = v.x;
                g_h[r * 128 + cc + 1] = v.y;
            }
        }
    }
}

// ================= scan: CSR ptr + dinv ======================================
__global__ void k_scan() {
    const int* cnt = (const int*)g_zbuf + HALF;
    const float* colsum = (const float*)g_zbuf;
    int t = threadIdx.x;
    int a = cnt[2 * t], b2 = cnt[2 * t + 1];
    int s = a + b2;
    int lane = t & 31, w = t >> 5;
    int v = s;
#pragma unroll
    for (int off = 1; off < 32; off <<= 1) {
        int u = __shfl_up_sync(0xffffffffu, v, off);
        if (lane >= off) v += u;
    }
    __shared__ int wsum[32];
    if (lane == 31) wsum[w] = v;
    __syncthreads();
    if (w == 0) {
        int xx = wsum[lane];
#pragma unroll
        for (int off = 1; off < 32; off <<= 1) {
            int u = __shfl_up_sync(0xffffffffu, xx, off);
            if (lane >= off) xx += u;
        }
        wsum[lane] = xx;
    }
    __syncthreads();
    int base = (w > 0) ? wsum[w - 1] : 0;
    int excl = base + v - s;
    g_ptr[2 * t] = excl;       g_ptr[2 * t + 1] = excl + a;
    g_cur[2 * t] = excl;       g_cur[2 * t + 1] = excl + a;
    if (t == 1023) g_ptr[NN] = ES;
    float d0 = 1.0f + (float)a  + (2 * t     < HALF ? colsum[2 * t]     : 0.f);
    float d1 = 1.0f + (float)b2 + (2 * t + 1 < HALF ? colsum[2 * t + 1] : 0.f);
    g_dinv[2 * t]     = rsqrtf(d0);
    g_dinv[2 * t + 1] = rsqrtf(d1);
}

// ================= CSR fill | hsd = dinv * h (float4) ========================
__global__ void k_fill_scale(const int* __restrict__ ei) {
    int b = blockIdx.x, tid = threadIdx.x;
    if (b < 256) {
        int e = b * 256 + tid;
        int dst = ei[ES + e];
        int pos = atomicAdd(&g_cur[dst], 1);
        g_csrc[pos] = ei[e];
    } else {
        int idx = (b - 256) * 256 + tid;            // float4 index
        float d = g_dinv[idx >> 5];
        float4 a = ((const float4*)g_h)[idx];
        a.x *= d; a.y *= d; a.z *= d; a.w *= d;
        ((float4*)g_hsd)[idx] = a;
    }
}

// ================= edge + self-loop aggregation (float4, 1 warp/node) ========
__global__ void __launch_bounds__(128, 8) k_agg_edge(const float* __restrict__ in) {
    const float4* in4 = (const float4*)in;
    int node = blockIdx.x * 4 + (threadIdx.x >> 5);
    int lane = threadIdx.x & 31;
    float4 acc = in4[node * 32 + lane];             // self loop (pre-scaled)
    int p = g_ptr[node], p1 = g_ptr[node + 1];
    for (; p + 8 <= p1; p += 8) {
        int s0 = g_csrc[p],     s1 = g_csrc[p + 1], s2 = g_csrc[p + 2], s3 = g_csrc[p + 3];
        int s4 = g_csrc[p + 4], s5 = g_csrc[p + 5], s6 = g_csrc[p + 6], s7 = g_csrc[p + 7];
        float4 v0 = in4[s0 * 32 + lane], v1 = in4[s1 * 32 + lane];
        float4 v2 = in4[s2 * 32 + lane], v3 = in4[s3 * 32 + lane];
        float4 v4 = in4[s4 * 32 + lane], v5 = in4[s5 * 32 + lane];
        float4 v6 = in4[s6 * 32 + lane], v7 = in4[s7 * 32 + lane];
        acc.x += ((v0.x + v1.x) + (v2.x + v3.x)) + ((v4.x + v5.x) + (v6.x + v7.x));
        acc.y += ((v0.y + v1.y) + (v2.y + v3.y)) + ((v4.y + v5.y) + (v6.y + v7.y));
        acc.z += ((v0.z + v1.z) + (v2.z + v3.z)) + ((v4.z + v5.z) + (v6.z + v7.z));
        acc.w += ((v0.w + v1.w) + (v2.w + v3.w)) + ((v4.w + v5.w) + (v6.w + v7.w));
    }
    for (; p < p1; p++) {
        float4 v = in4[g_csrc[p] * 32 + lane];
        acc.x += v.x; acc.y += v.y; acc.z += v.z; acc.w += v.w;
    }
    ((float4*)g_acc)[node * 32 + lane] = acc;       // plain store — initializes acc
}

// ================= dense aggregation: tf32 mma, red.v2 epilogue ==============
// g_acc[c, f] += sum_r S[r, c] * in[r, f]
// 256 blocks = 16 c-tiles x 2 f-halves x 8 k-splits. 256 thr = 8 warps (4m x 2n).
#define SAPAD 72
__global__ void __launch_bounds__(256) k_agg_dense(const float* __restrict__ in) {
    __shared__ float sA[32 * SAPAD];   // sA[k][m] = S[k0+k][c0+m]  (already tf32)
    __shared__ float sB[32 * SAPAD];   // sB[k][f] = tf32(in[k0+k][f0+f])
    int b = blockIdx.x;
    int c0 = (b & 15) * 64;
    int f0 = ((b >> 4) & 1) * 64;
    int kbase = (b >> 5) * 128;
    int tid = threadIdx.x;
    int wid = tid >> 5, lane = tid & 31;
    int wm = wid & 3, wn = wid >> 2;                // warp tile: 16 m x 32 n
    int g = lane >> 2, tg = lane & 3;
    float c[4][4] = {};
    for (int kt = 0; kt < 4; kt++) {
        int k0 = kbase + kt * 32;
        for (int l = tid; l < 2048; l += 256) {
            int k = l >> 6, m = l & 63;
            sA[k * SAPAD + m] = g_S[(k0 + k) * HALF + c0 + m];
        }
        for (int l = tid; l < 2048; l += 256) {
            int k = l >> 6, f = l & 63;
            sB[k * SAPAD + f] = cvt_tf32(in[(k0 + k) * F + f0 + f]);
        }
        __syncthreads();
#pragma unroll
        for (int ks = 0; ks < 4; ks++) {
            int kb = ks * 8;
            unsigned a0 = __float_as_uint(sA[(kb + tg) * SAPAD + wm * 16 + g]);
            unsigned a1 = __float_as_uint(sA[(kb + tg) * SAPAD + wm * 16 + g + 8]);
            unsigned a2 = __float_as_uint(sA[(kb + tg + 4) * SAPAD + wm * 16 + g]);
            unsigned a3 = __float_as_uint(sA[(kb + tg + 4) * SAPAD + wm * 16 + g + 8]);
#pragma unroll
            for (int nn = 0; nn < 4; nn++) {
                unsigned b0 = __float_as_uint(sB[(kb + tg) * SAPAD + wn * 32 + nn * 8 + g]);
                unsigned b1 = __float_as_uint(sB[(kb + tg + 4) * SAPAD + wn * 32 + nn * 8 + g]);
                asm("mma.sync.aligned.m16n8k8.row.col.f32.tf32.tf32.f32 "
                    "{%0,%1,%2,%3}, {%4,%5,%6,%7}, {%8,%9}, {%0,%1,%2,%3};"
                    : "+f"(c[nn][0]), "+f"(c[nn][1]), "+f"(c[nn][2]), "+f"(c[nn][3])
                    : "r"(a0), "r"(a1), "r"(a2), "r"(a3), "r"(b0), "r"(b1));
            }
        }
        __syncthreads();
    }
#pragma unroll
    for (int nn = 0; nn < 4; nn++) {
        int row = c0 + wm * 16 + g;
        int col = f0 + wn * 32 + nn * 8 + 2 * tg;
        float* p0 = &g_acc[row * F + col];
        float* p1 = &g_acc[(row + 8) * F + col];
        asm volatile("red.global.add.v2.f32 [%0], {%1, %2};"
                     :: "l"(p0), "f"(c[nn][0]), "f"(c[nn][1]) : "memory");
        asm volatile("red.global.add.v2.f32 [%0], {%1, %2};"
                     :: "l"(p1), "f"(c[nn][2]), "f"(c[nn][3]) : "memory");
    }
}

// ================= fin1: hsd = dinv*relu(dinv*acc + b1)  (float4) ============
__global__ void k_fin1(const float* __restrict__ b1) {
    int idx = blockIdx.x * 256 + threadIdx.x;       // float4 index
    float d = g_dinv[idx >> 5];
    int cb = (idx & 31) * 4;
    float4 a = ((const float4*)g_acc)[idx];
    float4 o;
    o.x = d * fmaxf(d * a.x + b1[cb],     0.f);
    o.y = d * fmaxf(d * a.y + b1[cb + 1], 0.f);
    o.z = d * fmaxf(d * a.z + b1[cb + 2], 0.f);
    o.w = d * fmaxf(d * a.w + b1[cb + 3], 0.f);
    ((float4*)g_hsd)[idx] = o;
}

// ================= output: [z_mu | z_logstd] = (dinv*acc) @ [Wmu|Wls] + bias ==
__global__ void __launch_bounds__(256) k_out(
        const float* __restrict__ Wmu, const float* __restrict__ bmu,
        const float* __restrict__ Wls, const float* __restrict__ bls,
        float* __restrict__ out) {
    __shared__ float As[16][33];
    __shared__ float Bs[16 * 128];
    int row0 = blockIdx.x * 32;
    int tid = threadIdx.x;
    int tx = tid & 15, ty = tid >> 4;
    unsigned long long acc[2][4] = {};
    for (int k0 = 0; k0 < 128; k0 += 16) {
        for (int l = tid; l < 32 * 16; l += 256) {
            int i = l >> 4, kk = l & 15;
            int r = row0 + i;
            As[kk][i] = g_acc[r * F + k0 + kk] * g_dinv[r];
        }
        for (int l = tid; l < 16 * 128; l += 256) {
            int kk = l >> 7, j = l & 127;
            Bs[kk * 128 + j] = (j < 64) ? Wmu[(k0 + kk) * LATD + j]
                                        : Wls[(k0 + kk) * LATD + (j - 64)];
        }
        __syncthreads();
#pragma unroll
        for (int kk = 0; kk < 16; kk++) {
            unsigned long long ad[2], bb[4];
#pragma unroll
            for (int m = 0; m < 2; m++) { float a = As[kk][ty + m * 16]; ad[m] = pk2(a, a); }
            const float2* brow = (const float2*)(Bs + kk * 128);
#pragma unroll
            for (int n = 0; n < 4; n++) { float2 bv = brow[tx + n * 16]; bb[n] = pk2(bv.x, bv.y); }
#pragma unroll
            for (int m = 0; m < 2; m++)
#pragma unroll
                for (int n = 0; n < 4; n++) fma2(acc[m][n], ad[m], bb[n]);
        }
        __syncthreads();
    }
#pragma unroll
    for (int m = 0; m < 2; m++) {
        int r = row0 + ty + m * 16;
#pragma unroll
        for (int n = 0; n < 4; n++) {
            float2 v = upk2(acc[m][n]);
            int j = 2 * (tx + n * 16);              // pairs never cross 64
            if (j < 64) {
                out[r * LATD + j]     = v.x + bmu[j];
                out[r * LATD + j + 1] = v.y + bmu[j + 1];
            } else {
                int jj = j - 64;
                out[NN * LATD + r * LATD + jj]     = v.x + bls[jj];
                out[NN * LATD + r * LATD + jj + 1] = v.y + bls[jj + 1];
            }
        }
    }
}

// ================= launch ====================================================
extern "C" void kernel_launch(void* const* d_in, const int* in_sizes, int n_in,
                              void* d_out, int out_size) {
    const float* x   = (const float*)d_in[0];
    const float* my  = (const float*)d_in[1];
    const float* W1  = (const float*)d_in[2];
    const float* b1  = (const float*)d_in[3];
    const float* Wmu = (const float*)d_in[4];
    const float* bmu = (const float*)d_in[5];
    const float* Wls = (const float*)d_in[6];
    const float* bls = (const float*)d_in[7];
    const int*   ei  = (const int*)d_in[8];
    float* out = (float*)d_out;

    void *p_zbuf, *p_hsd;
    cudaGetSymbolAddress(&p_zbuf, g_zbuf);
    cudaGetSymbolAddress(&p_hsd,  g_hsd);
    const float* hsd = (const float*)p_hsd;

    cudaMemsetAsync(p_zbuf, 0, (HALF + NN) * sizeof(int));

    k_megaA<<<1344, 256>>>(my, ei, x, W1);
    k_scan<<<1, 1024>>>();
    k_fill_scale<<<512, 256>>>(ei);

    // pass 1: edge (plain store) then dense (tensor-core, red.v2 add)
    k_agg_edge<<<NN / 4, 128>>>(hsd);
    k_agg_dense<<<256, 256>>>(hsd);
    k_fin1<<<256, 256>>>(b1);

    // pass 2
    k_agg_edge<<<NN / 4, 128>>>(hsd);
    k_agg_dense<<<256, 256>>>(hsd);

    k_out<<<64, 256>>>(Wmu, bmu, Wls, bls, out);
}

// round 8
// speedup vs baseline: 1.4311x; 1.0078x over previous
#include <cuda_runtime.h>

#define NN    2048
#define HALF  1024
#define F     128
#define LATD  64
#define ES    65536
#define KS    8

// ---------------- scratch (device globals) ----------------
__device__ unsigned g_zbuf[HALF + NN];   // [0,1024) colsum f32, [1024,3072) cnt i32
__device__ float g_S[HALF * HALF];       // tf32-rounded sigmoid(my[r,c]) at [r*1024+c]
__device__ float g_dinv[NN];
__device__ int   g_ptr[NN + 1];
__device__ int   g_cur[NN];
__device__ int   g_csrc[ES];
__device__ float g_h[NN * F];
__device__ float g_hsd[NN * F];
__device__ float g_acc[NN * F];
__device__ float g_part[KS * HALF * F];  // dense-agg partials (plain stores)

// ---------------- packed f32x2 helpers (SASS FFMA2) ----------------
__device__ __forceinline__ unsigned long long pk2(float lo, float hi) {
    unsigned long long r;
    asm("mov.b64 %0, {%1, %2};" : "=l"(r) : "f"(lo), "f"(hi));
    return r;
}
__device__ __forceinline__ float2 upk2(unsigned long long v) {
    float2 f;
    asm("mov.b64 {%0, %1}, %2;" : "=f"(f.x), "=f"(f.y) : "l"(v));
    return f;
}
__device__ __forceinline__ void fma2(unsigned long long& c,
                                     unsigned long long a, unsigned long long b) {
    asm("fma.rn.f32x2 %0, %1, %2, %3;" : "=l"(c) : "l"(a), "l"(b), "l"(c));
}
__device__ __forceinline__ float cvt_tf32(float v) {
    unsigned u;
    asm("cvt.rna.tf32.f32 %0, %1;" : "=r"(u) : "f"(v));
    return __uint_as_float(u);
}

// ================= mega kernel A: sigmoid+colsum | sparse count | gemm1 ======
__global__ void k_megaA(const float* __restrict__ my, const int* __restrict__ ei,
                        const float* __restrict__ x, const float* __restrict__ W1) {
    int b = blockIdx.x;
    int tid = threadIdx.x;
    if (b < 1024) {
        __shared__ float sm[256];
        int r0 = (b >> 5) * 32, c0 = (b & 31) * 32;
        int tx = tid & 31, ty = tid >> 5;
        int c = c0 + tx;
        float csum = 0.f;
#pragma unroll
        for (int rr = 0; rr < 4; rr++) {
            int r = r0 + ty + rr * 8;
            float v = cvt_tf32(1.0f / (1.0f + __expf(-my[r * 2048 + c])));
            g_S[r * HALF + c] = v;
            csum += v;
        }
        sm[tid] = csum;
        __syncthreads();
        if (ty < 4) sm[tid] += sm[tid + 128];
        __syncthreads();
        if (ty < 2) sm[tid] += sm[tid + 64];
        __syncthreads();
        if (ty == 0) atomicAdd(&((float*)g_zbuf)[c], sm[tid] + sm[tid + 32]);
    } else if (b < 1280) {
        int e = (b - 1024) * 256 + tid;
        atomicAdd((int*)g_zbuf + HALF + ei[ES + e], 1);
    } else {
        __shared__ float As[16][65];
        __shared__ float Bs[16 * 64];
        int bid = b - 1280;
        int col0 = (bid & 1) * 64;
        int row0 = (bid >> 1) * 64;
        int tx = tid & 15, ty = tid >> 4;
        unsigned long long acc[4][2] = {};
        for (int k0 = 0; k0 < 128; k0 += 16) {
            for (int l = tid; l < 64 * 16; l += 256) {
                int i = l >> 4, kk = l & 15;
                As[kk][i] = x[(row0 + i) * 128 + k0 + kk];
            }
            for (int l = tid; l < 16 * 64; l += 256) {
                int kk = l >> 6, j = l & 63;
                Bs[kk * 64 + j] = W1[(k0 + kk) * 128 + col0 + j];
            }
            __syncthreads();
#pragma unroll
            for (int kk = 0; kk < 16; kk++) {
                unsigned long long ad[4], bb[2];
#pragma unroll
                for (int m = 0; m < 4; m++) { float a = As[kk][ty + m * 16]; ad[m] = pk2(a, a); }
                const float2* brow = (const float2*)(Bs + kk * 64);
#pragma unroll
                for (int n = 0; n < 2; n++) { float2 bv = brow[tx + n * 16]; bb[n] = pk2(bv.x, bv.y); }
#pragma unroll
                for (int m = 0; m < 4; m++)
#pragma unroll
                    for (int n = 0; n < 2; n++) fma2(acc[m][n], ad[m], bb[n]);
            }
            __syncthreads();
        }
#pragma unroll
        for (int m = 0; m < 4; m++) {
            int r = row0 + ty + m * 16;
#pragma unroll
            for (int n = 0; n < 2; n++) {
                float2 v = upk2(acc[m][n]);
                int cc = col0 + 2 * (tx + n * 16);
                g_h[r * 128 + cc]     = v.x;
                g_h[r * 128 + cc + 1] = v.y;
            }
        }
    }
}

// ================= scan: CSR ptr + dinv ======================================
__global__ void k_scan() {
    const int* cnt = (const int*)g_zbuf + HALF;
    const float* colsum = (const float*)g_zbuf;
    int t = threadIdx.x;
    int a = cnt[2 * t], b2 = cnt[2 * t + 1];
    int s = a + b2;
    int lane = t & 31, w = t >> 5;
    int v = s;
#pragma unroll
    for (int off = 1; off < 32; off <<= 1) {
        int u = __shfl_up_sync(0xffffffffu, v, off);
        if (lane >= off) v += u;
    }
    __shared__ int wsum[32];
    if (lane == 31) wsum[w] = v;
    __syncthreads();
    if (w == 0) {
        int xx = wsum[lane];
#pragma unroll
        for (int off = 1; off < 32; off <<= 1) {
            int u = __shfl_up_sync(0xffffffffu, xx, off);
            if (lane >= off) xx += u;
        }
        wsum[lane] = xx;
    }
    __syncthreads();
    int base = (w > 0) ? wsum[w - 1] : 0;
    int excl = base + v - s;
    g_ptr[2 * t] = excl;       g_ptr[2 * t + 1] = excl + a;
    g_cur[2 * t] = excl;       g_cur[2 * t + 1] = excl + a;
    if (t == 1023) g_ptr[NN] = ES;
    float d0 = 1.0f + (float)a  + (2 * t     < HALF ? colsum[2 * t]     : 0.f);
    float d1 = 1.0f + (float)b2 + (2 * t + 1 < HALF ? colsum[2 * t + 1] : 0.f);
    g_dinv[2 * t]     = rsqrtf(d0);
    g_dinv[2 * t + 1] = rsqrtf(d1);
}

// ================= CSR fill | hsd = dinv * h (float4) ========================
__global__ void k_fill_scale(const int* __restrict__ ei) {
    int b = blockIdx.x, tid = threadIdx.x;
    if (b < 256) {
        int e = b * 256 + tid;
        int dst = ei[ES + e];
        int pos = atomicAdd(&g_cur[dst], 1);
        g_csrc[pos] = ei[e];
    } else {
        int idx = (b - 256) * 256 + tid;            // float4 index
        float d = g_dinv[idx >> 5];
        float4 a = ((const float4*)g_h)[idx];
        a.x *= d; a.y *= d; a.z *= d; a.w *= d;
        ((float4*)g_hsd)[idx] = a;
    }
}

// ================= edge + self-loop aggregation ==============================
// 256 threads = 8 warps = 4 nodes x 2 edge-halves. float4 per lane. smem combine.
__global__ void __launch_bounds__(256) k_agg_edge(const float* __restrict__ in) {
    __shared__ float4 sm[4][32];
    const float4* in4 = (const float4*)in;
    int wid = threadIdx.x >> 5, lane = threadIdx.x & 31;
    int nslot = wid >> 1;                            // 0..3
    int half = wid & 1;
    int node = blockIdx.x * 4 + nslot;
    int p0 = g_ptr[node], p1 = g_ptr[node + 1];
    int mid = p0 + ((p1 - p0) >> 1);
    int p, pe;
    float4 acc;
    if (half == 0) { p = p0; pe = mid; acc = in4[node * 32 + lane]; } // + self loop
    else           { p = mid; pe = p1; acc = make_float4(0.f, 0.f, 0.f, 0.f); }
    for (; p + 8 <= pe; p += 8) {
        int s0 = g_csrc[p],     s1 = g_csrc[p + 1], s2 = g_csrc[p + 2], s3 = g_csrc[p + 3];
        int s4 = g_csrc[p + 4], s5 = g_csrc[p + 5], s6 = g_csrc[p + 6], s7 = g_csrc[p + 7];
        float4 v0 = in4[s0 * 32 + lane], v1 = in4[s1 * 32 + lane];
        float4 v2 = in4[s2 * 32 + lane], v3 = in4[s3 * 32 + lane];
        float4 v4 = in4[s4 * 32 + lane], v5 = in4[s5 * 32 + lane];
        float4 v6 = in4[s6 * 32 + lane], v7 = in4[s7 * 32 + lane];
        acc.x += ((v0.x + v1.x) + (v2.x + v3.x)) + ((v4.x + v5.x) + (v6.x + v7.x));
        acc.y += ((v0.y + v1.y) + (v2.y + v3.y)) + ((v4.y + v5.y) + (v6.y + v7.y));
        acc.z += ((v0.z + v1.z) + (v2.z + v3.z)) + ((v4.z + v5.z) + (v6.z + v7.z));
        acc.w += ((v0.w + v1.w) + (v2.w + v3.w)) + ((v4.w + v5.w) + (v6.w + v7.w));
    }
    for (; p < pe; p++) {
        float4 v = in4[g_csrc[p] * 32 + lane];
        acc.x += v.x; acc.y += v.y; acc.z += v.z; acc.w += v.w;
    }
    if (half == 1) sm[nslot][lane] = acc;
    __syncthreads();
    if (half == 0) {
        float4 o = sm[nslot][lane];
        acc.x += o.x; acc.y += o.y; acc.z += o.z; acc.w += o.w;
        ((float4*)g_acc)[node * 32 + lane] = acc;   // plain store — initializes acc
    }
}

// ================= dense aggregation: tf32 mma, plain-store partials =========
// g_part[split][c, f-half] = S^T-slice @ in    (no atomics)
// 256 blocks = 16 c-tiles x 2 f-halves x 8 k-splits. 8 warps (4m x 2n).
#define SAPAD 72
__global__ void __launch_bounds__(256) k_agg_dense(const float* __restrict__ in) {
    __shared__ float sA[32 * SAPAD];   // sA[k][m] = S[k0+k][c0+m]  (already tf32)
    __shared__ float sB[32 * SAPAD];   // sB[k][f] = tf32(in[k0+k][f0+f])
    int b = blockIdx.x;
    int c0 = (b & 15) * 64;
    int f0 = ((b >> 4) & 1) * 64;
    int split = b >> 5;
    int kbase = split * 128;
    int tid = threadIdx.x;
    int wid = tid >> 5, lane = tid & 31;
    int wm = wid & 3, wn = wid >> 2;
    int g = lane >> 2, tg = lane & 3;
    float c[4][4] = {};
    for (int kt = 0; kt < 4; kt++) {
        int k0 = kbase + kt * 32;
        for (int l = tid; l < 2048; l += 256) {
            int k = l >> 6, m = l & 63;
            sA[k * SAPAD + m] = g_S[(k0 + k) * HALF + c0 + m];
        }
        for (int l = tid; l < 2048; l += 256) {
            int k = l >> 6, f = l & 63;
            sB[k * SAPAD + f] = cvt_tf32(in[(k0 + k) * F + f0 + f]);
        }
        __syncthreads();
#pragma unroll
        for (int ks = 0; ks < 4; ks++) {
            int kb = ks * 8;
            unsigned a0 = __float_as_uint(sA[(kb + tg) * SAPAD + wm * 16 + g]);
            unsigned a1 = __float_as_uint(sA[(kb + tg) * SAPAD + wm * 16 + g + 8]);
            unsigned a2 = __float_as_uint(sA[(kb + tg + 4) * SAPAD + wm * 16 + g]);
            unsigned a3 = __float_as_uint(sA[(kb + tg + 4) * SAPAD + wm * 16 + g + 8]);
#pragma unroll
            for (int nn = 0; nn < 4; nn++) {
                unsigned b0 = __float_as_uint(sB[(kb + tg) * SAPAD + wn * 32 + nn * 8 + g]);
                unsigned b1 = __float_as_uint(sB[(kb + tg + 4) * SAPAD + wn * 32 + nn * 8 + g]);
                asm("mma.sync.aligned.m16n8k8.row.col.f32.tf32.tf32.f32 "
                    "{%0,%1,%2,%3}, {%4,%5,%6,%7}, {%8,%9}, {%0,%1,%2,%3};"
                    : "+f"(c[nn][0]), "+f"(c[nn][1]), "+f"(c[nn][2]), "+f"(c[nn][3])
                    : "r"(a0), "r"(a1), "r"(a2), "r"(a3), "r"(b0), "r"(b1));
            }
        }
        __syncthreads();
    }
    float* dst = g_part + split * HALF * F;
#pragma unroll
    for (int nn = 0; nn < 4; nn++) {
        int row = c0 + wm * 16 + g;
        int col = f0 + wn * 32 + nn * 8 + 2 * tg;
        dst[row * F + col]           = c[nn][0];
        dst[row * F + col + 1]       = c[nn][1];
        dst[(row + 8) * F + col]     = c[nn][2];
        dst[(row + 8) * F + col + 1] = c[nn][3];
    }
}

// ================= fin1: reduce partials; hsd = dinv*relu(dinv*acc+b1) =======
__global__ void k_fin1(const float* __restrict__ b1) {
    int idx = blockIdx.x * 256 + threadIdx.x;       // float4 index (65536 total)
    float4 a = ((const float4*)g_acc)[idx];
    if (idx < HALF * F / 4) {
#pragma unroll
        for (int s = 0; s < KS; s++) {
            float4 pp = ((const float4*)g_part)[s * (HALF * F / 4) + idx];
            a.x += pp.x; a.y += pp.y; a.z += pp.z; a.w += pp.w;
        }
    }
    float d = g_dinv[idx >> 5];
    int cb = (idx & 31) * 4;
    float4 o;
    o.x = d * fmaxf(d * a.x + b1[cb],     0.f);
    o.y = d * fmaxf(d * a.y + b1[cb + 1], 0.f);
    o.z = d * fmaxf(d * a.z + b1[cb + 2], 0.f);
    o.w = d * fmaxf(d * a.w + b1[cb + 3], 0.f);
    ((float4*)g_hsd)[idx] = o;
}

// ================= output: [z_mu|z_logstd] = dinv*(acc+Σpart) @ [Wmu|Wls] ====
__global__ void __launch_bounds__(256) k_out(
        const float* __restrict__ Wmu, const float* __restrict__ bmu,
        const float* __restrict__ Wls, const float* __restrict__ bls,
        float* __restrict__ out) {
    __shared__ float As[16][33];
    __shared__ float Bs[16 * 128];
    int row0 = blockIdx.x * 32;
    bool firsthalf = row0 < HALF;
    int tid = threadIdx.x;
    int tx = tid & 15, ty = tid >> 4;
    unsigned long long acc[2][4] = {};
    for (int k0 = 0; k0 < 128; k0 += 16) {
        for (int l = tid; l < 32 * 16; l += 256) {
            int i = l >> 4, kk = l & 15;
            int r = row0 + i;
            float v = g_acc[r * F + k0 + kk];
            if (firsthalf) {
#pragma unroll
                for (int s = 0; s < KS; s++) v += g_part[s * HALF * F + r * F + k0 + kk];
            }
            As[kk][i] = v * g_dinv[r];
        }
        for (int l = tid; l < 16 * 128; l += 256) {
            int kk = l >> 7, j = l & 127;
            Bs[kk * 128 + j] = (j < 64) ? Wmu[(k0 + kk) * LATD + j]
                                        : Wls[(k0 + kk) * LATD + (j - 64)];
        }
        __syncthreads();
#pragma unroll
        for (int kk = 0; kk < 16; kk++) {
            unsigned long long ad[2], bb[4];
#pragma unroll
            for (int m = 0; m < 2; m++) { float a = As[kk][ty + m * 16]; ad[m] = pk2(a, a); }
            const float2* brow = (const float2*)(Bs + kk * 128);
#pragma unroll
            for (int n = 0; n < 4; n++) { float2 bv = brow[tx + n * 16]; bb[n] = pk2(bv.x, bv.y); }
#pragma unroll
            for (int m = 0; m < 2; m++)
#pragma unroll
                for (int n = 0; n < 4; n++) fma2(acc[m][n], ad[m], bb[n]);
        }
        __syncthreads();
    }
#pragma unroll
    for (int m = 0; m < 2; m++) {
        int r = row0 + ty + m * 16;
#pragma unroll
        for (int n = 0; n < 4; n++) {
            float2 v = upk2(acc[m][n]);
            int j = 2 * (tx + n * 16);              // pairs never cross 64
            if (j < 64) {
                out[r * LATD + j]     = v.x + bmu[j];
                out[r * LATD + j + 1] = v.y + bmu[j + 1];
            } else {
                int jj = j - 64;
                out[NN * LATD + r * LATD + jj]     = v.x + bls[jj];
                out[NN * LATD + r * LATD + jj + 1] = v.y + bls[jj + 1];
            }
        }
    }
}

// ================= launch ====================================================
extern "C" void kernel_launch(void* const* d_in, const int* in_sizes, int n_in,
                              void* d_out, int out_size) {
    const float* x   = (const float*)d_in[0];
    const float* my  = (const float*)d_in[1];
    const float* W1  = (const float*)d_in[2];
    const float* b1  = (const float*)d_in[3];
    const float* Wmu = (const float*)d_in[4];
    const float* bmu = (const float*)d_in[5];
    const float* Wls = (const float*)d_in[6];
    const float* bls = (const float*)d_in[7];
    const int*   ei  = (const int*)d_in[8];
    float* out = (float*)d_out;

    void *p_zbuf, *p_hsd;
    cudaGetSymbolAddress(&p_zbuf, g_zbuf);
    cudaGetSymbolAddress(&p_hsd,  g_hsd);
    const float* hsd = (const float*)p_hsd;

    cudaMemsetAsync(p_zbuf, 0, (HALF + NN) * sizeof(int));

    k_megaA<<<1344, 256>>>(my, ei, x, W1);
    k_scan<<<1, 1024>>>();
    k_fill_scale<<<512, 256>>>(ei);

    // pass 1: edge (plain store) and dense partials (plain store) — disjoint
    k_agg_edge<<<NN / 4, 256>>>(hsd);
    k_agg_dense<<<256, 256>>>(hsd);
    k_fin1<<<256, 256>>>(b1);

    // pass 2
    k_agg_edge<<<NN / 4, 256>>>(hsd);
    k_agg_dense<<<256, 256>>>(hsd);

    k_out<<<64, 256>>>(Wmu, bmu, Wls, bls, out);
}

// round 9
// speedup vs baseline: 1.4549x; 1.0166x over previous
#include <cuda_runtime.h>

#define NN    2048
#define HALF  1024
#define F     128
#define LATD  64
#define ES    65536
#define KS    8

// ---------------- scratch (device globals) ----------------
__device__ unsigned g_zbuf[HALF + NN];   // [0,1024) colsum f32, [1024,3072) cnt i32
__device__ float g_S[HALF * HALF];       // tf32-rounded sigmoid(my[r,c]) at [r*1024+c]
__device__ float g_dinv[NN];
__device__ int   g_ptr[NN + 1];
__device__ int   g_cur[NN];
__device__ int   g_csrc[ES];
__device__ float g_h[NN * F];
__device__ float g_hsd[NN * F];
__device__ float g_acc[NN * F];
__device__ float g_part[KS * HALF * F];  // dense-agg partials (plain stores)

// ---------------- packed f32x2 helpers (SASS FFMA2) ----------------
__device__ __forceinline__ unsigned long long pk2(float lo, float hi) {
    unsigned long long r;
    asm("mov.b64 %0, {%1, %2};" : "=l"(r) : "f"(lo), "f"(hi));
    return r;
}
__device__ __forceinline__ float2 upk2(unsigned long long v) {
    float2 f;
    asm("mov.b64 {%0, %1}, %2;" : "=f"(f.x), "=f"(f.y) : "l"(v));
    return f;
}
__device__ __forceinline__ void fma2(unsigned long long& c,
                                     unsigned long long a, unsigned long long b) {
    asm("fma.rn.f32x2 %0, %1, %2, %3;" : "=l"(c) : "l"(a), "l"(b), "l"(c));
}
__device__ __forceinline__ float cvt_tf32(float v) {
    unsigned u;
    asm("cvt.rna.tf32.f32 %0, %1;" : "=r"(u) : "f"(v));
    return __uint_as_float(u);
}
__device__ __forceinline__ float fast_sigmoid(float x) {
    // sigmoid(x) = 0.5*tanh(x/2) + 0.5 : one MUFU instead of RCP+EX2
    float t;
    asm("tanh.approx.f32 %0, %1;" : "=f"(t) : "f"(0.5f * x));
    return fmaf(0.5f, t, 0.5f);
}

// ================= mega kernel A: sigmoid+colsum | sparse count | gemm1 ======
__global__ void k_megaA(const float* __restrict__ my, const int* __restrict__ ei,
                        const float* __restrict__ x, const float* __restrict__ W1) {
    int b = blockIdx.x;
    int tid = threadIdx.x;
    if (b < 1024) {
        __shared__ float sm[256];
        int r0 = (b >> 5) * 32, c0 = (b & 31) * 32;
        int tx = tid & 31, ty = tid >> 5;
        int c = c0 + tx;
        float csum = 0.f;
#pragma unroll
        for (int rr = 0; rr < 4; rr++) {
            int r = r0 + ty + rr * 8;
            float v = cvt_tf32(fast_sigmoid(my[r * 2048 + c]));
            g_S[r * HALF + c] = v;
            csum += v;
        }
        sm[tid] = csum;
        __syncthreads();
        if (ty < 4) sm[tid] += sm[tid + 128];
        __syncthreads();
        if (ty < 2) sm[tid] += sm[tid + 64];
        __syncthreads();
        if (ty == 0) atomicAdd(&((float*)g_zbuf)[c], sm[tid] + sm[tid + 32]);
    } else if (b < 1280) {
        int e = (b - 1024) * 256 + tid;
        atomicAdd((int*)g_zbuf + HALF + ei[ES + e], 1);
    } else {
        __shared__ float As[16][65];
        __shared__ float Bs[16 * 64];
        int bid = b - 1280;
        int col0 = (bid & 1) * 64;
        int row0 = (bid >> 1) * 64;
        int tx = tid & 15, ty = tid >> 4;
        unsigned long long acc[4][2] = {};
        for (int k0 = 0; k0 < 128; k0 += 16) {
            for (int l = tid; l < 64 * 16; l += 256) {
                int i = l >> 4, kk = l & 15;
                As[kk][i] = x[(row0 + i) * 128 + k0 + kk];
            }
            for (int l = tid; l < 16 * 64; l += 256) {
                int kk = l >> 6, j = l & 63;
                Bs[kk * 64 + j] = W1[(k0 + kk) * 128 + col0 + j];
            }
            __syncthreads();
#pragma unroll
            for (int kk = 0; kk < 16; kk++) {
                unsigned long long ad[4], bb[2];
#pragma unroll
                for (int m = 0; m < 4; m++) { float a = As[kk][ty + m * 16]; ad[m] = pk2(a, a); }
                const float2* brow = (const float2*)(Bs + kk * 64);
#pragma unroll
                for (int n = 0; n < 2; n++) { float2 bv = brow[tx + n * 16]; bb[n] = pk2(bv.x, bv.y); }
#pragma unroll
                for (int m = 0; m < 4; m++)
#pragma unroll
                    for (int n = 0; n < 2; n++) fma2(acc[m][n], ad[m], bb[n]);
            }
            __syncthreads();
        }
#pragma unroll
        for (int m = 0; m < 4; m++) {
            int r = row0 + ty + m * 16;
#pragma unroll
            for (int n = 0; n < 2; n++) {
                float2 v = upk2(acc[m][n]);
                int cc = col0 + 2 * (tx + n * 16);
                g_h[r * 128 + cc]     = v.x;
                g_h[r * 128 + cc + 1] = v.y;
            }
        }
    }
}

// ================= scan: CSR ptr + dinv ======================================
__global__ void k_scan() {
    const int* cnt = (const int*)g_zbuf + HALF;
    const float* colsum = (const float*)g_zbuf;
    int t = threadIdx.x;
    int a = cnt[2 * t], b2 = cnt[2 * t + 1];
    int s = a + b2;
    int lane = t & 31, w = t >> 5;
    int v = s;
#pragma unroll
    for (int off = 1; off < 32; off <<= 1) {
        int u = __shfl_up_sync(0xffffffffu, v, off);
        if (lane >= off) v += u;
    }
    __shared__ int wsum[32];
    if (lane == 31) wsum[w] = v;
    __syncthreads();
    if (w == 0) {
        int xx = wsum[lane];
#pragma unroll
        for (int off = 1; off < 32; off <<= 1) {
            int u = __shfl_up_sync(0xffffffffu, xx, off);
            if (lane >= off) xx += u;
        }
        wsum[lane] = xx;
    }
    __syncthreads();
    int base = (w > 0) ? wsum[w - 1] : 0;
    int excl = base + v - s;
    g_ptr[2 * t] = excl;       g_ptr[2 * t + 1] = excl + a;
    g_cur[2 * t] = excl;       g_cur[2 * t + 1] = excl + a;
    if (t == 1023) g_ptr[NN] = ES;
    float d0 = 1.0f + (float)a  + (2 * t     < HALF ? colsum[2 * t]     : 0.f);
    float d1 = 1.0f + (float)b2 + (2 * t + 1 < HALF ? colsum[2 * t + 1] : 0.f);
    g_dinv[2 * t]     = rsqrtf(d0);
    g_dinv[2 * t + 1] = rsqrtf(d1);
}

// ================= CSR fill | hsd = dinv * h (float4) ========================
__global__ void k_fill_scale(const int* __restrict__ ei) {
    int b = blockIdx.x, tid = threadIdx.x;
    if (b < 256) {
        int e = b * 256 + tid;
        int dst = ei[ES + e];
        int pos = atomicAdd(&g_cur[dst], 1);
        g_csrc[pos] = ei[e];
    } else {
        int idx = (b - 256) * 256 + tid;            // float4 index
        float d = g_dinv[idx >> 5];
        float4 a = ((const float4*)g_h)[idx];
        a.x *= d; a.y *= d; a.z *= d; a.w *= d;
        ((float4*)g_hsd)[idx] = a;
    }
}

// ================= edge + self-loop aggregation ==============================
// 256 threads = 8 warps = 2 nodes x 4 edge-quarters. float4 per lane.
__global__ void __launch_bounds__(256) k_agg_edge(const float* __restrict__ in) {
    __shared__ float4 sm[2][3][32];
    const float4* in4 = (const float4*)in;
    int wid = threadIdx.x >> 5, lane = threadIdx.x & 31;
    int slot = wid >> 2;                             // 0..1
    int q = wid & 3;                                 // 0..3
    int node = blockIdx.x * 2 + slot;
    int p0 = g_ptr[node], p1 = g_ptr[node + 1];
    int len = p1 - p0;
    int p  = p0 + ((len * q) >> 2);
    int pe = p0 + ((len * (q + 1)) >> 2);
    float4 acc;
    if (q == 0) acc = in4[node * 32 + lane];         // self loop (pre-scaled)
    else        acc = make_float4(0.f, 0.f, 0.f, 0.f);
    for (; p + 4 <= pe; p += 4) {
        int s0 = g_csrc[p], s1 = g_csrc[p + 1], s2 = g_csrc[p + 2], s3 = g_csrc[p + 3];
        float4 v0 = in4[s0 * 32 + lane], v1 = in4[s1 * 32 + lane];
        float4 v2 = in4[s2 * 32 + lane], v3 = in4[s3 * 32 + lane];
        acc.x += (v0.x + v1.x) + (v2.x + v3.x);
        acc.y += (v0.y + v1.y) + (v2.y + v3.y);
        acc.z += (v0.z + v1.z) + (v2.z + v3.z);
        acc.w += (v0.w + v1.w) + (v2.w + v3.w);
    }
    for (; p < pe; p++) {
        float4 v = in4[g_csrc[p] * 32 + lane];
        acc.x += v.x; acc.y += v.y; acc.z += v.z; acc.w += v.w;
    }
    if (q != 0) sm[slot][q - 1][lane] = acc;
    __syncthreads();
    if (q == 0) {
        float4 o1 = sm[slot][0][lane], o2 = sm[slot][1][lane], o3 = sm[slot][2][lane];
        acc.x += (o1.x + o2.x) + o3.x;
        acc.y += (o1.y + o2.y) + o3.y;
        acc.z += (o1.z + o2.z) + o3.z;
        acc.w += (o1.w + o2.w) + o3.w;
        ((float4*)g_acc)[node * 32 + lane] = acc;   // plain store — initializes acc
    }
}

// ================= dense aggregation: tf32 mma, plain-store partials =========
#define SAPAD 72
__global__ void __launch_bounds__(256) k_agg_dense(const float* __restrict__ in) {
    __shared__ float sA[32 * SAPAD];   // sA[k][m] = S[k0+k][c0+m]  (already tf32)
    __shared__ float sB[32 * SAPAD];   // sB[k][f] = tf32(in[k0+k][f0+f])
    int b = blockIdx.x;
    int c0 = (b & 15) * 64;
    int f0 = ((b >> 4) & 1) * 64;
    int split = b >> 5;
    int kbase = split * 128;
    int tid = threadIdx.x;
    int wid = tid >> 5, lane = tid & 31;
    int wm = wid & 3, wn = wid >> 2;
    int g = lane >> 2, tg = lane & 3;
    float c[4][4] = {};
    for (int kt = 0; kt < 4; kt++) {
        int k0 = kbase + kt * 32;
        for (int l = tid; l < 2048; l += 256) {
            int k = l >> 6, m = l & 63;
            sA[k * SAPAD + m] = g_S[(k0 + k) * HALF + c0 + m];
        }
        for (int l = tid; l < 2048; l += 256) {
            int k = l >> 6, f = l & 63;
            sB[k * SAPAD + f] = cvt_tf32(in[(k0 + k) * F + f0 + f]);
        }
        __syncthreads();
#pragma unroll
        for (int ks = 0; ks < 4; ks++) {
            int kb = ks * 8;
            unsigned a0 = __float_as_uint(sA[(kb + tg) * SAPAD + wm * 16 + g]);
            unsigned a1 = __float_as_uint(sA[(kb + tg) * SAPAD + wm * 16 + g + 8]);
            unsigned a2 = __float_as_uint(sA[(kb + tg + 4) * SAPAD + wm * 16 + g]);
            unsigned a3 = __float_as_uint(sA[(kb + tg + 4) * SAPAD + wm * 16 + g + 8]);
#pragma unroll
            for (int nn = 0; nn < 4; nn++) {
                unsigned b0 = __float_as_uint(sB[(kb + tg) * SAPAD + wn * 32 + nn * 8 + g]);
                unsigned b1 = __float_as_uint(sB[(kb + tg + 4) * SAPAD + wn * 32 + nn * 8 + g]);
                asm("mma.sync.aligned.m16n8k8.row.col.f32.tf32.tf32.f32 "
                    "{%0,%1,%2,%3}, {%4,%5,%6,%7}, {%8,%9}, {%0,%1,%2,%3};"
                    : "+f"(c[nn][0]), "+f"(c[nn][1]), "+f"(c[nn][2]), "+f"(c[nn][3])
                    : "r"(a0), "r"(a1), "r"(a2), "r"(a3), "r"(b0), "r"(b1));
            }
        }
        __syncthreads();
    }
    float* dst = g_part + split * HALF * F;
#pragma unroll
    for (int nn = 0; nn < 4; nn++) {
        int row = c0 + wm * 16 + g;
        int col = f0 + wn * 32 + nn * 8 + 2 * tg;
        dst[row * F + col]           = c[nn][0];
        dst[row * F + col + 1]       = c[nn][1];
        dst[(row + 8) * F + col]     = c[nn][2];
        dst[(row + 8) * F + col + 1] = c[nn][3];
    }
}

// ================= fin1: reduce partials; hsd = dinv*relu(dinv*acc+b1) =======
__global__ void k_fin1(const float* __restrict__ b1) {
    int idx = blockIdx.x * 256 + threadIdx.x;       // float4 index (65536 total)
    float4 a = ((const float4*)g_acc)[idx];
    if (idx < HALF * F / 4) {
#pragma unroll
        for (int s = 0; s < KS; s++) {
            float4 pp = ((const float4*)g_part)[s * (HALF * F / 4) + idx];
            a.x += pp.x; a.y += pp.y; a.z += pp.z; a.w += pp.w;
        }
    }
    float d = g_dinv[idx >> 5];
    int cb = (idx & 31) * 4;
    float4 o;
    o.x = d * fmaxf(d * a.x + b1[cb],     0.f);
    o.y = d * fmaxf(d * a.y + b1[cb + 1], 0.f);
    o.z = d * fmaxf(d * a.z + b1[cb + 2], 0.f);
    o.w = d * fmaxf(d * a.w + b1[cb + 3], 0.f);
    ((float4*)g_hsd)[idx] = o;
}

// ================= output: [z_mu|z_logstd] = dinv*(acc+Σpart) @ [Wmu|Wls] ====
__global__ void __launch_bounds__(256) k_out(
        const float* __restrict__ Wmu, const float* __restrict__ bmu,
        const float* __restrict__ Wls, const float* __restrict__ bls,
        float* __restrict__ out) {
    __shared__ float As[16][33];
    __shared__ float Bs[16 * 128];
    int row0 = blockIdx.x * 32;
    bool firsthalf = row0 < HALF;
    int tid = threadIdx.x;
    int tx = tid & 15, ty = tid >> 4;
    unsigned long long acc[2][4] = {};
    for (int k0 = 0; k0 < 128; k0 += 16) {
        for (int l = tid; l < 32 * 16; l += 256) {
            int i = l >> 4, kk = l & 15;
            int r = row0 + i;
            float v = g_acc[r * F + k0 + kk];
            if (firsthalf) {
#pragma unroll
                for (int s = 0; s < KS; s++) v += g_part[s * HALF * F + r * F + k0 + kk];
            }
            As[kk][i] = v * g_dinv[r];
        }
        for (int l = tid; l < 16 * 128; l += 256) {
            int kk = l >> 7, j = l & 127;
            Bs[kk * 128 + j] = (j < 64) ? Wmu[(k0 + kk) * LATD + j]
                                        : Wls[(k0 + kk) * LATD + (j - 64)];
        }
        __syncthreads();
#pragma unroll
        for (int kk = 0; kk < 16; kk++) {
            unsigned long long ad[2], bb[4];
#pragma unroll
            for (int m = 0; m < 2; m++) { float a = As[kk][ty + m * 16]; ad[m] = pk2(a, a); }
            const float2* brow = (const float2*)(Bs + kk * 128);
#pragma unroll
            for (int n = 0; n < 4; n++) { float2 bv = brow[tx + n * 16]; bb[n] = pk2(bv.x, bv.y); }
#pragma unroll
            for (int m = 0; m < 2; m++)
#pragma unroll
                for (int n = 0; n < 4; n++) fma2(acc[m][n], ad[m], bb[n]);
        }
        __syncthreads();
    }
#pragma unroll
    for (int m = 0; m < 2; m++) {
        int r = row0 + ty + m * 16;
#pragma unroll
        for (int n = 0; n < 4; n++) {
            float2 v = upk2(acc[m][n]);
            int j = 2 * (tx + n * 16);              // pairs never cross 64
            if (j < 64) {
                out[r * LATD + j]     = v.x + bmu[j];
                out[r * LATD + j + 1] = v.y + bmu[j + 1];
            } else {
                int jj = j - 64;
                out[NN * LATD + r * LATD + jj]     = v.x + bls[jj];
                out[NN * LATD + r * LATD + jj + 1] = v.y + bls[jj + 1];
            }
        }
    }
}

// ================= launch ====================================================
extern "C" void kernel_launch(void* const* d_in, const int* in_sizes, int n_in,
                              void* d_out, int out_size) {
    const float* x   = (const float*)d_in[0];
    const float* my  = (const float*)d_in[1];
    const float* W1  = (const float*)d_in[2];
    const float* b1  = (const float*)d_in[3];
    const float* Wmu = (const float*)d_in[4];
    const float* bmu = (const float*)d_in[5];
    const float* Wls = (const float*)d_in[6];
    const float* bls = (const float*)d_in[7];
    const int*   ei  = (const int*)d_in[8];
    float* out = (float*)d_out;

    void *p_zbuf, *p_hsd;
    cudaGetSymbolAddress(&p_zbuf, g_zbuf);
    cudaGetSymbolAddress(&p_hsd,  g_hsd);
    const float* hsd = (const float*)p_hsd;

    cudaMemsetAsync(p_zbuf, 0, (HALF + NN) * sizeof(int));

    k_megaA<<<1344, 256>>>(my, ei, x, W1);
    k_scan<<<1, 1024>>>();
    k_fill_scale<<<512, 256>>>(ei);

    // pass 1: edge (plain store) and dense partials (plain store) — disjoint
    k_agg_edge<<<NN / 2, 256>>>(hsd);
    k_agg_dense<<<256, 256>>>(hsd);
    k_fin1<<<256, 256>>>(b1);

    // pass 2
    k_agg_edge<<<NN / 2, 256>>>(hsd);
    k_agg_dense<<<256, 256>>>(hsd);

    k_out<<<64, 256>>>(Wmu, bmu, Wls, bls, out);
}

// round 10
// speedup vs baseline: 1.5828x; 1.0880x over previous
#include <cuda_runtime.h>

#define NN    2048
#define HALF  1024
#define F     128
#define LATD  64
#define ES    65536
#define KS    8

// ---------------- scratch (device globals) ----------------
// g_zbuf invariant: ZERO at entry to kernel_launch (module-load zero-init;
// k_scan re-zeroes it after consuming, so every call restores the invariant).
__device__ unsigned g_zbuf[HALF + NN];   // [0,1024) colsum f32, [1024,3072) cnt i32
__device__ float g_S[HALF * HALF];       // tf32-rounded sigmoid(my[r,c]) at [r*1024+c]
__device__ float g_dinv[NN];
__device__ int   g_ptr[NN + 1];
__device__ int   g_cur[NN];
__device__ int   g_csrc[ES];
__device__ float g_h[NN * F];
__device__ float g_hsd[NN * F];
__device__ float g_acc[NN * F];
__device__ float g_part[KS * HALF * F];  // dense-agg partials (plain stores)

// ---------------- packed f32x2 helpers (SASS FFMA2) ----------------
__device__ __forceinline__ unsigned long long pk2(float lo, float hi) {
    unsigned long long r;
    asm("mov.b64 %0, {%1, %2};" : "=l"(r) : "f"(lo), "f"(hi));
    return r;
}
__device__ __forceinline__ float2 upk2(unsigned long long v) {
    float2 f;
    asm("mov.b64 {%0, %1}, %2;" : "=f"(f.x), "=f"(f.y) : "l"(v));
    return f;
}
__device__ __forceinline__ void fma2(unsigned long long& c,
                                     unsigned long long a, unsigned long long b) {
    asm("fma.rn.f32x2 %0, %1, %2, %3;" : "=l"(c) : "l"(a), "l"(b), "l"(c));
}
__device__ __forceinline__ float cvt_tf32(float v) {
    unsigned u;
    asm("cvt.rna.tf32.f32 %0, %1;" : "=r"(u) : "f"(v));
    return __uint_as_float(u);
}
__device__ __forceinline__ float fast_sigmoid(float x) {
    float t;
    asm("tanh.approx.f32 %0, %1;" : "=f"(t) : "f"(0.5f * x));
    return fmaf(0.5f, t, 0.5f);
}

// ================= mega kernel A: gemm1 | sigmoid+colsum | sparse count ======
// GEMM blocks FIRST so the longest blocks start at wave 0.
__global__ void k_megaA(const float* __restrict__ my, const int* __restrict__ ei,
                        const float* __restrict__ x, const float* __restrict__ W1) {
    int b = blockIdx.x;
    int tid = threadIdx.x;
    if (b < 64) {
        // gemm1: g_h = x @ W1   (2048x128x128), BM=64 BN=64
        __shared__ float As[16][65];
        __shared__ float Bs[16 * 64];
        int col0 = (b & 1) * 64;
        int row0 = (b >> 1) * 64;
        int tx = tid & 15, ty = tid >> 4;
        unsigned long long acc[4][2] = {};
        for (int k0 = 0; k0 < 128; k0 += 16) {
            for (int l = tid; l < 64 * 16; l += 256) {
                int i = l >> 4, kk = l & 15;
                As[kk][i] = x[(row0 + i) * 128 + k0 + kk];
            }
            for (int l = tid; l < 16 * 64; l += 256) {
                int kk = l >> 6, j = l & 63;
                Bs[kk * 64 + j] = W1[(k0 + kk) * 128 + col0 + j];
            }
            __syncthreads();
#pragma unroll
            for (int kk = 0; kk < 16; kk++) {
                unsigned long long ad[4], bb[2];
#pragma unroll
                for (int m = 0; m < 4; m++) { float a = As[kk][ty + m * 16]; ad[m] = pk2(a, a); }
                const float2* brow = (const float2*)(Bs + kk * 64);
#pragma unroll
                for (int n = 0; n < 2; n++) { float2 bv = brow[tx + n * 16]; bb[n] = pk2(bv.x, bv.y); }
#pragma unroll
                for (int m = 0; m < 4; m++)
#pragma unroll
                    for (int n = 0; n < 2; n++) fma2(acc[m][n], ad[m], bb[n]);
            }
            __syncthreads();
        }
#pragma unroll
        for (int m = 0; m < 4; m++) {
            int r = row0 + ty + m * 16;
#pragma unroll
            for (int n = 0; n < 2; n++) {
                float2 v = upk2(acc[m][n]);
                int cc = col0 + 2 * (tx + n * 16);
                g_h[r * 128 + cc]     = v.x;
                g_h[r * 128 + cc + 1] = v.y;
            }
        }
    } else if (b < 1088) {
        int t = b - 64;
        __shared__ float sm[256];
        int r0 = (t >> 5) * 32, c0 = (t & 31) * 32;
        int tx = tid & 31, ty = tid >> 5;
        int c = c0 + tx;
        float csum = 0.f;
#pragma unroll
        for (int rr = 0; rr < 4; rr++) {
            int r = r0 + ty + rr * 8;
            float v = cvt_tf32(fast_sigmoid(my[r * 2048 + c]));
            g_S[r * HALF + c] = v;
            csum += v;
        }
        sm[tid] = csum;
        __syncthreads();
        if (ty < 4) sm[tid] += sm[tid + 128];
        __syncthreads();
        if (ty < 2) sm[tid] += sm[tid + 64];
        __syncthreads();
        if (ty == 0) atomicAdd(&((float*)g_zbuf)[c], sm[tid] + sm[tid + 32]);
    } else {
        int e = (b - 1088) * 256 + tid;
        atomicAdd((int*)g_zbuf + HALF + ei[ES + e], 1);
    }
}

// ================= scan: CSR ptr + dinv; then re-zero g_zbuf =================
__global__ void k_scan() {
    const int* cnt = (const int*)g_zbuf + HALF;
    const float* colsum = (const float*)g_zbuf;
    int t = threadIdx.x;
    int a = cnt[2 * t], b2 = cnt[2 * t + 1];
    int s = a + b2;
    int lane = t & 31, w = t >> 5;
    int v = s;
#pragma unroll
    for (int off = 1; off < 32; off <<= 1) {
        int u = __shfl_up_sync(0xffffffffu, v, off);
        if (lane >= off) v += u;
    }
    __shared__ int wsum[32];
    if (lane == 31) wsum[w] = v;
    __syncthreads();
    if (w == 0) {
        int xx = wsum[lane];
#pragma unroll
        for (int off = 1; off < 32; off <<= 1) {
            int u = __shfl_up_sync(0xffffffffu, xx, off);
            if (lane >= off) xx += u;
        }
        wsum[lane] = xx;
    }
    __syncthreads();
    int base = (w > 0) ? wsum[w - 1] : 0;
    int excl = base + v - s;
    g_ptr[2 * t] = excl;       g_ptr[2 * t + 1] = excl + a;
    g_cur[2 * t] = excl;       g_cur[2 * t + 1] = excl + a;
    if (t == 1023) g_ptr[NN] = ES;
    float d0 = 1.0f + (float)a  + (2 * t     < HALF ? colsum[2 * t]     : 0.f);
    float d1 = 1.0f + (float)b2 + (2 * t + 1 < HALF ? colsum[2 * t + 1] : 0.f);
    g_dinv[2 * t]     = rsqrtf(d0);
    g_dinv[2 * t + 1] = rsqrtf(d1);
    // restore zbuf=0 invariant for the next call (all reads above are done)
    __syncthreads();
    g_zbuf[t] = 0u; g_zbuf[t + 1024] = 0u; g_zbuf[t + 2048] = 0u;
}

// ================= CSR fill | hsd = dinv * h (float4) ========================
__global__ void k_fill_scale(const int* __restrict__ ei) {
    int b = blockIdx.x, tid = threadIdx.x;
    if (b < 256) {
        int e = b * 256 + tid;
        int dst = ei[ES + e];
        int pos = atomicAdd(&g_cur[dst], 1);
        g_csrc[pos] = ei[e];
    } else {
        int idx = (b - 256) * 256 + tid;            // float4 index
        float d = g_dinv[idx >> 5];
        float4 a = ((const float4*)g_h)[idx];
        a.x *= d; a.y *= d; a.z *= d; a.w *= d;
        ((float4*)g_hsd)[idx] = a;
    }
}

// ================= fused aggregation: dense MMA | edge CSR ==================
// blocks [0,256): dense tf32 mma -> g_part (plain stores)
// blocks [256,2304): edge, 1 node per block, 8 warps = 8 edge-eighths
#define SAPAD 72
__global__ void __launch_bounds__(256) k_agg(const float* __restrict__ in) {
    __shared__ __align__(16) float sA[32 * SAPAD];
    __shared__ __align__(16) float sB[32 * SAPAD];
    int b = blockIdx.x;
    int tid = threadIdx.x;
    if (b < 256) {
        int c0 = (b & 15) * 64;
        int f0 = ((b >> 4) & 1) * 64;
        int split = b >> 5;
        int kbase = split * 128;
        int wid = tid >> 5, lane = tid & 31;
        int wm = wid & 3, wn = wid >> 2;
        int g = lane >> 2, tg = lane & 3;
        float c[4][4] = {};
        for (int kt = 0; kt < 4; kt++) {
            int k0 = kbase + kt * 32;
            for (int l = tid; l < 2048; l += 256) {
                int k = l >> 6, m = l & 63;
                sA[k * SAPAD + m] = g_S[(k0 + k) * HALF + c0 + m];
            }
            for (int l = tid; l < 2048; l += 256) {
                int k = l >> 6, f = l & 63;
                sB[k * SAPAD + f] = cvt_tf32(in[(k0 + k) * F + f0 + f]);
            }
            __syncthreads();
#pragma unroll
            for (int ks = 0; ks < 4; ks++) {
                int kb = ks * 8;
                unsigned a0 = __float_as_uint(sA[(kb + tg) * SAPAD + wm * 16 + g]);
                unsigned a1 = __float_as_uint(sA[(kb + tg) * SAPAD + wm * 16 + g + 8]);
                unsigned a2 = __float_as_uint(sA[(kb + tg + 4) * SAPAD + wm * 16 + g]);
                unsigned a3 = __float_as_uint(sA[(kb + tg + 4) * SAPAD + wm * 16 + g + 8]);
#pragma unroll
                for (int nn = 0; nn < 4; nn++) {
                    unsigned b0 = __float_as_uint(sB[(kb + tg) * SAPAD + wn * 32 + nn * 8 + g]);
                    unsigned b1 = __float_as_uint(sB[(kb + tg + 4) * SAPAD + wn * 32 + nn * 8 + g]);
                    asm("mma.sync.aligned.m16n8k8.row.col.f32.tf32.tf32.f32 "
                        "{%0,%1,%2,%3}, {%4,%5,%6,%7}, {%8,%9}, {%0,%1,%2,%3};"
                        : "+f"(c[nn][0]), "+f"(c[nn][1]), "+f"(c[nn][2]), "+f"(c[nn][3])
                        : "r"(a0), "r"(a1), "r"(a2), "r"(a3), "r"(b0), "r"(b1));
                }
            }
            __syncthreads();
        }
        float* dst = g_part + split * HALF * F;
#pragma unroll
        for (int nn = 0; nn < 4; nn++) {
            int row = c0 + wm * 16 + g;
            int col = f0 + wn * 32 + nn * 8 + 2 * tg;
            dst[row * F + col]           = c[nn][0];
            dst[row * F + col + 1]       = c[nn][1];
            dst[(row + 8) * F + col]     = c[nn][2];
            dst[(row + 8) * F + col + 1] = c[nn][3];
        }
    } else {
        // edge: one node, 8 warps each take 1/8 of the edge list (~4 edges)
        float4* smE = (float4*)sA;                   // 7*32 float4 = 3.5 KB
        const float4* in4 = (const float4*)in;
        int node = b - 256;
        int wid = tid >> 5, lane = tid & 31;
        int p0 = g_ptr[node], p1 = g_ptr[node + 1];
        int len = p1 - p0;
        int p  = p0 + ((len * wid) >> 3);
        int pe = p0 + ((len * (wid + 1)) >> 3);
        float4 acc;
        if (wid == 0) acc = in4[node * 32 + lane];   // self loop (pre-scaled)
        else          acc = make_float4(0.f, 0.f, 0.f, 0.f);
        for (; p + 4 <= pe; p += 4) {
            int s0 = g_csrc[p], s1 = g_csrc[p + 1], s2 = g_csrc[p + 2], s3 = g_csrc[p + 3];
            float4 v0 = in4[s0 * 32 + lane], v1 = in4[s1 * 32 + lane];
            float4 v2 = in4[s2 * 32 + lane], v3 = in4[s3 * 32 + lane];
            acc.x += (v0.x + v1.x) + (v2.x + v3.x);
            acc.y += (v0.y + v1.y) + (v2.y + v3.y);
            acc.z += (v0.z + v1.z) + (v2.z + v3.z);
            acc.w += (v0.w + v1.w) + (v2.w + v3.w);
        }
        for (; p < pe; p++) {
            float4 v = in4[g_csrc[p] * 32 + lane];
            acc.x += v.x; acc.y += v.y; acc.z += v.z; acc.w += v.w;
        }
        if (wid != 0) smE[(wid - 1) * 32 + lane] = acc;
        __syncthreads();
        if (wid == 0) {
            float4 o0 = smE[0 * 32 + lane], o1 = smE[1 * 32 + lane];
            float4 o2 = smE[2 * 32 + lane], o3 = smE[3 * 32 + lane];
            float4 o4 = smE[4 * 32 + lane], o5 = smE[5 * 32 + lane];
            float4 o6 = smE[6 * 32 + lane];
            acc.x += ((o0.x + o1.x) + (o2.x + o3.x)) + ((o4.x + o5.x) + o6.x);
            acc.y += ((o0.y + o1.y) + (o2.y + o3.y)) + ((o4.y + o5.y) + o6.y);
            acc.z += ((o0.z + o1.z) + (o2.z + o3.z)) + ((o4.z + o5.z) + o6.z);
            acc.w += ((o0.w + o1.w) + (o2.w + o3.w)) + ((o4.w + o5.w) + o6.w);
            ((float4*)g_acc)[node * 32 + lane] = acc;  // plain store — inits acc
        }
    }
}

// ================= fin1: reduce partials; hsd = dinv*relu(dinv*acc+b1) =======
__global__ void k_fin1(const float* __restrict__ b1) {
    int idx = blockIdx.x * 256 + threadIdx.x;       // float4 index (65536 total)
    float4 a = ((const float4*)g_acc)[idx];
    if (idx < HALF * F / 4) {
#pragma unroll
        for (int s = 0; s < KS; s++) {
            float4 pp = ((const float4*)g_part)[s * (HALF * F / 4) + idx];
            a.x += pp.x; a.y += pp.y; a.z += pp.z; a.w += pp.w;
        }
    }
    float d = g_dinv[idx >> 5];
    int cb = (idx & 31) * 4;
    float4 o;
    o.x = d * fmaxf(d * a.x + b1[cb],     0.f);
    o.y = d * fmaxf(d * a.y + b1[cb + 1], 0.f);
    o.z = d * fmaxf(d * a.z + b1[cb + 2], 0.f);
    o.w = d * fmaxf(d * a.w + b1[cb + 3], 0.f);
    ((float4*)g_hsd)[idx] = o;
}

// ================= output: [z_mu|z_logstd] = dinv*(acc+Σpart) @ [Wmu|Wls] ====
__global__ void __launch_bounds__(256) k_out(
        const float* __restrict__ Wmu, const float* __restrict__ bmu,
        const float* __restrict__ Wls, const float* __restrict__ bls,
        float* __restrict__ out) {
    __shared__ float As[16][33];
    __shared__ float Bs[16 * 128];
    int row0 = blockIdx.x * 32;
    bool firsthalf = row0 < HALF;
    int tid = threadIdx.x;
    int tx = tid & 15, ty = tid >> 4;
    unsigned long long acc[2][4] = {};
    for (int k0 = 0; k0 < 128; k0 += 16) {
        for (int l = tid; l < 32 * 16; l += 256) {
            int i = l >> 4, kk = l & 15;
            int r = row0 + i;
            float v = g_acc[r * F + k0 + kk];
            if (firsthalf) {
#pragma unroll
                for (int s = 0; s < KS; s++) v += g_part[s * HALF * F + r * F + k0 + kk];
            }
            As[kk][i] = v * g_dinv[r];
        }
        for (int l = tid; l < 16 * 128; l += 256) {
            int kk = l >> 7, j = l & 127;
            Bs[kk * 128 + j] = (j < 64) ? Wmu[(k0 + kk) * LATD + j]
                                        : Wls[(k0 + kk) * LATD + (j - 64)];
        }
        __syncthreads();
#pragma unroll
        for (int kk = 0; kk < 16; kk++) {
            unsigned long long ad[2], bb[4];
#pragma unroll
            for (int m = 0; m < 2; m++) { float a = As[kk][ty + m * 16]; ad[m] = pk2(a, a); }
            const float2* brow = (const float2*)(Bs + kk * 128);
#pragma unroll
            for (int n = 0; n < 4; n++) { float2 bv = brow[tx + n * 16]; bb[n] = pk2(bv.x, bv.y); }
#pragma unroll
            for (int m = 0; m < 2; m++)
#pragma unroll
                for (int n = 0; n < 4; n++) fma2(acc[m][n], ad[m], bb[n]);
        }
        __syncthreads();
    }
#pragma unroll
    for (int m = 0; m < 2; m++) {
        int r = row0 + ty + m * 16;
#pragma unroll
        for (int n = 0; n < 4; n++) {
            float2 v = upk2(acc[m][n]);
            int j = 2 * (tx + n * 16);              // pairs never cross 64
            if (j < 64) {
                out[r * LATD + j]     = v.x + bmu[j];
                out[r * LATD + j + 1] = v.y + bmu[j + 1];
            } else {
                int jj = j - 64;
                out[NN * LATD + r * LATD + jj]     = v.x + bls[jj];
                out[NN * LATD + r * LATD + jj + 1] = v.y + bls[jj + 1];
            }
        }
    }
}

// ================= launch: 7 nodes ==========================================
extern "C" void kernel_launch(void* const* d_in, const int* in_sizes, int n_in,
                              void* d_out, int out_size) {
    const float* x   = (const float*)d_in[0];
    const float* my  = (const float*)d_in[1];
    const float* W1  = (const float*)d_in[2];
    const float* b1  = (const float*)d_in[3];
    const float* Wmu = (const float*)d_in[4];
    const float* bmu = (const float*)d_in[5];
    const float* Wls = (const float*)d_in[6];
    const float* bls = (const float*)d_in[7];
    const int*   ei  = (const int*)d_in[8];
    float* out = (float*)d_out;

    void* p_hsd;
    cudaGetSymbolAddress(&p_hsd, g_hsd);
    const float* hsd = (const float*)p_hsd;

    k_megaA<<<1344, 256>>>(my, ei, x, W1);
    k_scan<<<1, 1024>>>();
    k_fill_scale<<<512, 256>>>(ei);

    k_agg<<<2304, 256>>>(hsd);      // pass 1: dense partials + edge acc
    k_fin1<<<256, 256>>>(b1);
    k_agg<<<2304, 256>>>(hsd);      // pass 2

    k_out<<<64, 256>>>(Wmu, bmu, Wls, bls, out);
}